// round 1
// baseline (speedup 1.0000x reference)
#include <cuda_runtime.h>
#include <math.h>

// Problem constants (fixed by the dataset)
constexpr int Bn = 4096, Tn = 32, Xn = 256, Hn = 256, Zn = 256, Gn = 128, Yn = 2;
constexpr int BT = Bn * Tn; // 131072

// ---------------- static device scratch (no allocations allowed) ----------------
__device__ float g_AX [131072 * 1280];  // x-projections: [r,u,h,zp,zq] each 256 wide
__device__ float g_CAT[131072 * 768];   // packed [x | h | z] for the output GEMM
__device__ float g_H  [33 * 4096 * 256]; // h states, slot t holds h_{t-1}; slot 0 = h0
__device__ float g_Z  [33 * 4096 * 256]; // z states, slot 0 = z0
__device__ float g_R  [4096 * 256];
__device__ float g_U  [4096 * 256];
__device__ float g_HZP[4096 * 256];
__device__ float g_HZQ[4096 * 256];
__device__ float g_HD [4096 * 1024];    // [mu_p | lp | mu_q | lq]
__device__ float g_G  [131072 * 128];

#define DI __device__ __forceinline__

DI float sigf(float x) { return 1.0f / (1.0f + expf(-x)); }

// ---------------- B operand descriptor: up to 5 column segments of width 256 -----
struct BDesc { const float* p[5]; int ld[5]; };

// ---------------- A loaders ----------------
struct APlain {
    const float* p; int ld;
    DI float4 ld4(int r, int k, int) const {
        return *(const float4*)(p + (size_t)r * ld + k);
    }
};
struct ACat2 { // [h_prev | z_prev], both ld=256
    const float* a; const float* b;
    DI float4 ld4(int r, int k, int) const {
        const float* q = (k < 256) ? (a + (size_t)r * 256 + k) : (b + (size_t)r * 256 + (k - 256));
        return *(const float4*)q;
    }
};
struct ACat2Mul { // [r*h_prev | z_prev]
    const float* rg; const float* h; const float* z;
    DI float4 ld4(int r, int k, int) const {
        if (k < 256) {
            float4 rv = *(const float4*)(rg + (size_t)r * 256 + k);
            float4 hv = *(const float4*)(h  + (size_t)r * 256 + k);
            return make_float4(rv.x * hv.x, rv.y * hv.y, rv.z * hv.z, rv.w * hv.w);
        }
        return *(const float4*)(z + (size_t)r * 256 + (k - 256));
    }
};
struct ASel { // A depends on which N-segment the block covers (heads GEMM)
    const float* a0; const float* a1;
    DI float4 ld4(int r, int k, int nseg) const {
        const float* q = (nseg < 2 ? a0 : a1) + (size_t)r * 256 + k;
        return *(const float4*)q;
    }
};

// ---------------- Epilogues ----------------
struct EP_AX { // phase-1 x-projections (+bias, + y rank-2 term for zq segment)
    float* AX; const float* bias[5]; const float* yph; const float* WzqY;
    DI void operator()(int row, int col, float acc) const {
        int seg = col >> 8, c = col & 255;
        float v = acc + bias[seg][c];
        if (seg == 4)
            v += yph[(size_t)row * 2] * WzqY[c] + yph[(size_t)row * 2 + 1] * WzqY[256 + c];
        AX[(size_t)row * 1280 + col] = v;
    }
};
struct EP_RU {
    const float* AX; float* R; float* U; int t;
    DI void operator()(int b, int col, float acc) const {
        size_t bt = (size_t)b * Tn + t;
        if (col < 256) R[b * 256 + col]       = sigf(acc + AX[bt * 1280 + col]);
        else           U[b * 256 + col - 256] = sigf(acc + AX[bt * 1280 + col]); // col in [256,512) == AX seg 1
    }
};
struct EP_H {
    const float* AX; const float* U; const float* hp; float* Hout; float* CAT; int t;
    DI void operator()(int b, int c, float acc) const {
        size_t bt = (size_t)b * Tn + t;
        float ht = tanhf(acc + AX[bt * 1280 + 512 + c]);
        float u  = U[b * 256 + c];
        float h0 = hp[b * 256 + c];
        float h  = (1.0f - u) * h0 + u * ht;
        Hout[b * 256 + c] = h;
        CAT[bt * 768 + 256 + c] = h;
    }
};
struct EP_ZPQ {
    const float* AX; float* HZP; float* HZQ; int t;
    DI void operator()(int b, int col, float acc) const {
        size_t bt = (size_t)b * Tn + t;
        if (col < 256) HZP[b * 256 + col]       = tanhf(acc + AX[bt * 1280 + 768 + col]);
        else           HZQ[b * 256 + col - 256] = tanhf(acc + AX[bt * 1280 + 1024 + (col - 256)]);
    }
};
struct EP_HEADS {
    float* HD; const float* bias[4];
    DI void operator()(int b, int col, float acc) const {
        int seg = col >> 8, c = col & 255;
        HD[(size_t)b * 1024 + col] = acc + bias[seg][c];
    }
};
struct EP_G {
    float* G; const float* bg;
    DI void operator()(int row, int col, float acc) const {
        G[(size_t)row * 128 + col] = tanhf(acc + bg[col]);
    }
};

// ---------------- Tiled fp32 GEMM: 128x64x16, double-buffered ----------------
template <class AL, class EP>
__global__ __launch_bounds__(256)
void gemm_tpl(AL al, EP ep, BDesc bd, int K) {
    constexpr int BM = 128, BN = 64, BK = 16;
    __shared__ float As[2][BK][BM + 4];
    __shared__ float Bs[2][BK][BN];

    const int tid  = threadIdx.x;
    const int m0   = blockIdx.y * BM;
    const int n0   = blockIdx.x * BN;
    const int nseg = n0 >> 8;
    const float* bp = bd.p[nseg];
    const int bld   = bd.ld[nseg];
    const int bc0   = n0 & 255;

    const int arow = tid >> 2;        // 0..63 (second load at +64)
    const int akq  = (tid & 3) * 4;   // k offset 0,4,8,12
    const int bk   = tid >> 4;        // 0..15
    const int bc   = (tid & 15) * 4;  // 0..60

    const int ty = tid >> 4;          // 0..15 -> 8 rows each
    const int tx = tid & 15;          // 0..15 -> 4 cols each

    float acc[8][4];
#pragma unroll
    for (int i = 0; i < 8; i++)
#pragma unroll
        for (int j = 0; j < 4; j++) acc[i][j] = 0.0f;

    float4 ra0 = al.ld4(m0 + arow,      akq, nseg);
    float4 ra1 = al.ld4(m0 + arow + 64, akq, nseg);
    float4 rb  = *(const float4*)(bp + (size_t)bk * bld + bc0 + bc);

    As[0][akq + 0][arow] = ra0.x; As[0][akq + 1][arow] = ra0.y;
    As[0][akq + 2][arow] = ra0.z; As[0][akq + 3][arow] = ra0.w;
    As[0][akq + 0][arow + 64] = ra1.x; As[0][akq + 1][arow + 64] = ra1.y;
    As[0][akq + 2][arow + 64] = ra1.z; As[0][akq + 3][arow + 64] = ra1.w;
    *(float4*)&Bs[0][bk][bc] = rb;
    __syncthreads();

    const int nk = K / BK;
    for (int kt = 0; kt < nk; kt++) {
        const int cur = kt & 1;
        if (kt + 1 < nk) {
            int k0 = (kt + 1) * BK;
            ra0 = al.ld4(m0 + arow,      k0 + akq, nseg);
            ra1 = al.ld4(m0 + arow + 64, k0 + akq, nseg);
            rb  = *(const float4*)(bp + (size_t)(k0 + bk) * bld + bc0 + bc);
        }
#pragma unroll
        for (int kk = 0; kk < BK; kk++) {
            float4 av0 = *(const float4*)&As[cur][kk][ty * 8];
            float4 av1 = *(const float4*)&As[cur][kk][ty * 8 + 4];
            float4 bv  = *(const float4*)&Bs[cur][kk][tx * 4];
            float a[8] = {av0.x, av0.y, av0.z, av0.w, av1.x, av1.y, av1.z, av1.w};
            float b[4] = {bv.x, bv.y, bv.z, bv.w};
#pragma unroll
            for (int i = 0; i < 8; i++)
#pragma unroll
                for (int j = 0; j < 4; j++)
                    acc[i][j] = fmaf(a[i], b[j], acc[i][j]);
        }
        if (kt + 1 < nk) {
            const int nxt = cur ^ 1;
            As[nxt][akq + 0][arow] = ra0.x; As[nxt][akq + 1][arow] = ra0.y;
            As[nxt][akq + 2][arow] = ra0.z; As[nxt][akq + 3][arow] = ra0.w;
            As[nxt][akq + 0][arow + 64] = ra1.x; As[nxt][akq + 1][arow + 64] = ra1.y;
            As[nxt][akq + 2][arow + 64] = ra1.z; As[nxt][akq + 3][arow + 64] = ra1.w;
            *(float4*)&Bs[nxt][bk][bc] = rb;
        }
        __syncthreads();
    }

#pragma unroll
    for (int i = 0; i < 8; i++) {
        int row = m0 + ty * 8 + i;
#pragma unroll
        for (int j = 0; j < 4; j++)
            ep(row, n0 + tx * 4 + j, acc[i][j]);
    }
}

// ---------------- small kernels ----------------
__global__ void init_copy(const float* __restrict__ x, const float* __restrict__ h0,
                          const float* __restrict__ z0, float* __restrict__ CAT,
                          float* __restrict__ Hb, float* __restrict__ Zb) {
    size_t idx = (size_t)blockIdx.x * blockDim.x + threadIdx.x; // exactly BT*Xn threads
    size_t r = idx >> 8, k = idx & 255;
    CAT[r * 768 + k] = x[idx];
    if (idx < (size_t)Bn * Hn) { Hb[idx] = h0[idx]; Zb[idx] = z0[idx]; }
}

__global__ void step_latent(const float* __restrict__ HD, const float* __restrict__ eps_t,
                            float* __restrict__ Zout, float* __restrict__ CAT,
                            float* __restrict__ outKL, int t) {
    int b = blockIdx.x, c = threadIdx.x; // 256 threads
    size_t hb = (size_t)b * 1024;
    float mup = HD[hb + c];
    float lp  = HD[hb + 256 + c];
    float muq = HD[hb + 512 + c];
    float lq  = HD[hb + 768 + c];
    float z = muq + expf(0.5f * lq) * eps_t[b * 256 + c];
    Zout[b * 256 + c] = z;
    size_t bt = (size_t)b * Tn + t;
    CAT[bt * 768 + 512 + c] = z;
    float d = muq - mup;
    float kl = 0.5f * (lp - lq) + (expf(lq) + d * d) / (2.0f * expf(lp)) - 0.5f;

    __shared__ float red[8];
    for (int o = 16; o; o >>= 1) kl += __shfl_down_sync(0xffffffffu, kl, o);
    if ((threadIdx.x & 31) == 0) red[threadIdx.x >> 5] = kl;
    __syncthreads();
    if (threadIdx.x == 0) {
        float s = 0.0f;
#pragma unroll
        for (int i = 0; i < 8; i++) s += red[i];
        outKL[bt] = s;
    }
}

__global__ void yhead(const float* __restrict__ G, const float* __restrict__ Wy,
                      const float* __restrict__ by, float* __restrict__ outY) {
    int r = blockIdx.x * 8 + (threadIdx.x >> 5); // warp per row
    int lane = threadIdx.x & 31;
    float s0 = 0.0f, s1 = 0.0f;
    const float* g = G + (size_t)r * 128;
    for (int k = lane; k < 128; k += 32) {
        float gv = g[k];
        s0 += gv * Wy[k * 2];
        s1 += gv * Wy[k * 2 + 1];
    }
    for (int o = 16; o; o >>= 1) {
        s0 += __shfl_down_sync(0xffffffffu, s0, o);
        s1 += __shfl_down_sync(0xffffffffu, s1, o);
    }
    if (lane == 0) {
        float l0 = s0 + by[0], l1 = s1 + by[1];
        float m = fmaxf(l0, l1);
        float e0 = expf(l0 - m), e1 = expf(l1 - m);
        float inv = 1.0f / (e0 + e1);
        outY[(size_t)r * 2]     = e0 * inv;
        outY[(size_t)r * 2 + 1] = e1 * inv;
    }
}

__global__ void gatherGT(const float* __restrict__ G, const int* __restrict__ Tph,
                         float* __restrict__ outGT) {
    int b = blockIdx.x;
    int t = Tph[b] - 1;
    outGT[(size_t)b * Gn + threadIdx.x] = G[((size_t)b * Tn + t) * Gn + threadIdx.x];
}

// ---------------- launch ----------------
extern "C" void kernel_launch(void* const* d_in, const int* in_sizes, int n_in,
                              void* d_out, int out_size) {
    const float* x   = (const float*)d_in[0];
    const float* yph = (const float*)d_in[1];
    const int*   Tph = (const int*)  d_in[2];
    const float* h0  = (const float*)d_in[3];
    const float* z0  = (const float*)d_in[4];
    const float* eps = (const float*)d_in[5];
    const float* Wr  = (const float*)d_in[6];  const float* br  = (const float*)d_in[7];
    const float* Wu  = (const float*)d_in[8];  const float* bu  = (const float*)d_in[9];
    const float* Wh  = (const float*)d_in[10]; const float* bh  = (const float*)d_in[11];
    const float* Wzp = (const float*)d_in[12]; const float* bzp = (const float*)d_in[13];
    const float* Wpm = (const float*)d_in[14]; const float* bpm = (const float*)d_in[15];
    const float* Wps = (const float*)d_in[16]; const float* bps = (const float*)d_in[17];
    const float* Wzq = (const float*)d_in[18]; const float* bzq = (const float*)d_in[19];
    const float* Wqm = (const float*)d_in[20]; const float* bqm = (const float*)d_in[21];
    const float* Wqs = (const float*)d_in[22]; const float* bqs = (const float*)d_in[23];
    const float* Wg  = (const float*)d_in[24]; const float* bg  = (const float*)d_in[25];
    const float* Wy  = (const float*)d_in[26]; const float* by  = (const float*)d_in[27];

    float *AX, *CAT, *Hb, *Zb, *Rb, *Ub, *HZP, *HZQ, *HD, *Gb;
    {
        void* p;
        cudaGetSymbolAddress(&p, g_AX);  AX  = (float*)p;
        cudaGetSymbolAddress(&p, g_CAT); CAT = (float*)p;
        cudaGetSymbolAddress(&p, g_H);   Hb  = (float*)p;
        cudaGetSymbolAddress(&p, g_Z);   Zb  = (float*)p;
        cudaGetSymbolAddress(&p, g_R);   Rb  = (float*)p;
        cudaGetSymbolAddress(&p, g_U);   Ub  = (float*)p;
        cudaGetSymbolAddress(&p, g_HZP); HZP = (float*)p;
        cudaGetSymbolAddress(&p, g_HZQ); HZQ = (float*)p;
        cudaGetSymbolAddress(&p, g_HD);  HD  = (float*)p;
        cudaGetSymbolAddress(&p, g_G);   Gb  = (float*)p;
    }

    float* out   = (float*)d_out;
    float* outY  = out;                 // [B*T, 2]
    float* outKL = out + (size_t)BT * Yn;       // [B*T]
    float* outGT = out + (size_t)BT * Yn + BT;  // [B, G]

    // init: pack x into CAT, seed h0/z0
    init_copy<<<BT, 256>>>(x, h0, z0, CAT, Hb, Zb);

    // phase 1: all x-projections in one GEMM  [131072,256] @ [256,1280]
    {
        APlain al{x, Xn};
        BDesc bd{};
        bd.p[0] = Wr;  bd.p[1] = Wu;  bd.p[2] = Wh;  bd.p[3] = Wzp; bd.p[4] = Wzq;
        for (int i = 0; i < 5; i++) bd.ld[i] = 256;
        EP_AX ep;
        ep.AX = AX;
        ep.bias[0] = br; ep.bias[1] = bu; ep.bias[2] = bh; ep.bias[3] = bzp; ep.bias[4] = bzq;
        ep.yph = yph; ep.WzqY = Wzq + 512 * 256;
        gemm_tpl<<<dim3(1280 / 64, BT / 128), 256>>>(al, ep, bd, 256);
    }

    // phase 2: sequential scan over T
    for (int t = 0; t < Tn; t++) {
        const float* hp = Hb + (size_t)t * Bn * Hn;
        const float* zp = Zb + (size_t)t * Bn * Zn;
        float* hn = Hb + (size_t)(t + 1) * Bn * Hn;
        float* zn = Zb + (size_t)(t + 1) * Bn * Zn;

        { // gates r,u: [hp|zp] @ [Wr_hz | Wu_hz]
            ACat2 al{hp, zp};
            BDesc bd{};
            bd.p[0] = Wr + Xn * Hn; bd.ld[0] = Hn;
            bd.p[1] = Wu + Xn * Hn; bd.ld[1] = Hn;
            EP_RU ep{AX, Rb, Ub, t};
            gemm_tpl<<<dim3(512 / 64, Bn / 128), 256>>>(al, ep, bd, 512);
        }
        { // candidate + GRU update: [r*hp|zp] @ Wh_hz
            ACat2Mul al{Rb, hp, zp};
            BDesc bd{};
            bd.p[0] = Wh + Xn * Hn; bd.ld[0] = Hn;
            EP_H ep{AX, Ub, hp, hn, CAT, t};
            gemm_tpl<<<dim3(256 / 64, Bn / 128), 256>>>(al, ep, bd, 512);
        }
        { // latent hiddens: h @ [Wzp_h | Wzq_h]
            APlain al{hn, Hn};
            BDesc bd{};
            bd.p[0] = Wzp + Xn * Zn; bd.ld[0] = Zn;
            bd.p[1] = Wzq + Xn * Zn; bd.ld[1] = Zn;
            EP_ZPQ ep{AX, HZP, HZQ, t};
            gemm_tpl<<<dim3(512 / 64, Bn / 128), 256>>>(al, ep, bd, 256);
        }
        { // heads: mu_p, lp from hzp; mu_q, lq from hzq
            ASel al{HZP, HZQ};
            BDesc bd{};
            bd.p[0] = Wpm; bd.p[1] = Wps; bd.p[2] = Wqm; bd.p[3] = Wqs;
            for (int i = 0; i < 4; i++) bd.ld[i] = 256;
            EP_HEADS ep;
            ep.HD = HD;
            ep.bias[0] = bpm; ep.bias[1] = bps; ep.bias[2] = bqm; ep.bias[3] = bqs;
            gemm_tpl<<<dim3(1024 / 64, Bn / 128), 256>>>(al, ep, bd, 256);
        }
        // reparam + KL reduce
        step_latent<<<Bn, 256>>>(HD, eps + (size_t)t * Bn * Zn, zn, CAT, outKL, t);
    }

    // phase 3: g = tanh(CAT @ Wg + bg)
    {
        APlain al{CAT, 768};
        BDesc bd{};
        bd.p[0] = Wg; bd.ld[0] = Gn;
        EP_G ep{Gb, bg};
        gemm_tpl<<<dim3(Gn / 64, BT / 128), 256>>>(al, ep, bd, 768);
    }
    // y = softmax(g @ Wy + by); g_T gather
    yhead<<<BT / 8, 256>>>(Gb, Wy, by, outY);
    gatherGT<<<Bn, Gn>>>(Gb, Tph, outGT);
}